// round 1
// baseline (speedup 1.0000x reference)
#include <cuda_runtime.h>
#include <math.h>

#define BB 4
#define NN 2048
#define EE (NN*(NN-1)/2)        // 2,096,128
#define NBLK (BB*NN)            // 8192
#define TPB 256

// Per-(b,row) partial sums. Every slot is written every launch (row 0 writes 0),
// so no init pass is needed and the result is deterministic (no atomics).
__device__ double g_partial[NBLK];

__global__ __launch_bounds__(TPB) void diffusion_row_kernel(
    const int*   __restrict__ adj,   // [B, N, N] int32
    const int*   __restrict__ t,     // [B] int32
    const float* __restrict__ u,     // [B, N, N] f32
    const float* __restrict__ q)     // [B, E] f32
{
    const int i   = blockIdx.x;      // row index 0..N-1
    const int b   = blockIdx.y;      // batch
    const int tid = threadIdx.x;

    // Per-batch flip probabilities. Qt[t] -> ts = t+1; Qt[t-1] wraps to Qt[999] when t==0.
    const int tb = t[b];
    const float f  = 0.5f * (1.0f - (float)pow(0.98, (double)(tb + 1)));
    const int  tp = (tb == 0) ? (1000 - 1) : (tb - 1);
    const float fp = 0.5f * (1.0f - (float)pow(0.98, (double)(tp + 1)));

    const float omf  = 1.0f - f;
    const float omfp = 1.0f - fp;

    const int*   arow = adj + ((size_t)b * NN + i) * NN;
    const float* urow = u   + ((size_t)b * NN + i) * NN;
    const float* qrow = q   + (size_t)b * EE + (size_t)i * (i - 1) / 2;

    float s = 0.0f;
    for (int j = tid; j < i; j += TPB) {
        const int   a  = arow[j];
        const float uu = urow[j];
        const float xv = qrow[j];

        const float p1  = a ? omf : f;          // P(x_t = 1)
        const bool  x   = uu < p1;
        const float lik = x ? 0.99f : 0.01f;    // Qt[0][x_t, 1]
        const float pr  = a ? omfp : fp;        // Qt[t-1][a, 1]
        const float ev  = ((a != 0) == x) ? omf : f;  // Qt[t][a, x_t]
        const float qt  = lik * pr / ev;

        // BCE-with-logits style term
        s += fmaxf(xv, 0.0f) - xv * qt + log1pf(__expf(-fabsf(xv)));
    }

    // block reduction
    __shared__ float sh[TPB];
    sh[tid] = s;
    __syncthreads();
    #pragma unroll
    for (int o = TPB / 2; o > 0; o >>= 1) {
        if (tid < o) sh[tid] += sh[tid + o];
        __syncthreads();
    }
    if (tid == 0) g_partial[(size_t)b * NN + i] = (double)sh[0];
}

__global__ __launch_bounds__(TPB) void diffusion_reduce_kernel(float* __restrict__ out)
{
    __shared__ double sh[TPB];
    double s = 0.0;
    for (int idx = threadIdx.x; idx < NBLK; idx += TPB) s += g_partial[idx];
    sh[threadIdx.x] = s;
    __syncthreads();
    #pragma unroll
    for (int o = TPB / 2; o > 0; o >>= 1) {
        if (threadIdx.x < o) sh[threadIdx.x] += sh[threadIdx.x + o];
        __syncthreads();
    }
    if (threadIdx.x == 0)
        out[0] = (float)(sh[0] / ((double)BB * (double)EE));
}

extern "C" void kernel_launch(void* const* d_in, const int* in_sizes, int n_in,
                              void* d_out, int out_size)
{
    const int*   adj = (const int*)  d_in[0];   // adj_start [B,N,N] int32
    const int*   t   = (const int*)  d_in[1];   // t [B] int32
    const float* u   = (const float*)d_in[2];   // u [B,N,N] f32
    const float* q   = (const float*)d_in[3];   // q_approx [B,E] f32
    float* out = (float*)d_out;

    dim3 grid(NN, BB);
    diffusion_row_kernel<<<grid, TPB>>>(adj, t, u, q);
    diffusion_reduce_kernel<<<1, TPB>>>(out);
}

// round 2
// speedup vs baseline: 13.7611x; 13.7611x over previous
#include <cuda_runtime.h>
#include <math.h>

#define BB 4
#define NN 2048
#define EE (NN*(NN-1)/2)        // 2,096,128
#define NBLK (BB*NN)            // 8192
#define TPB 256

__device__ float  g_f[BB];      // flip prob at t   : 0.5*(1-0.98^(t+1))
__device__ float  g_fp[BB];     // flip prob at t-1 (wrapped)
__device__ double g_partial[NBLK];

// One-time per-launch: 4 threads compute the per-batch constants (fp64 pow is
// fine here — it runs 4 times total, not 2.1M times).
__global__ void diffusion_setup_kernel(const int* __restrict__ t)
{
    const int b = threadIdx.x;
    if (b < BB) {
        const int tb = t[b];
        g_f[b]  = 0.5f * (float)(1.0 - pow(0.98, (double)(tb + 1)));
        const int tp = (tb == 0) ? 999 : (tb - 1);
        g_fp[b] = 0.5f * (float)(1.0 - pow(0.98, (double)(tp + 1)));
    }
}

__device__ __forceinline__ float edge_term(int a, float uu, float xv,
                                           float f, float omf, float fp, float omfp)
{
    const float p1  = a ? omf : f;               // P(x_t = 1)
    const bool  x   = uu < p1;
    const float lik = x ? 0.99f : 0.01f;         // Qt[0][x_t, 1]
    const float pr  = a ? omfp : fp;             // Qt[t-1][a, 1]
    const float ev  = ((a != 0) == x) ? omf : f; // Qt[t][a, x_t]
    const float qt  = lik * pr / ev;
    return fmaxf(xv, 0.0f) - xv * qt + log1pf(__expf(-fabsf(xv)));
}

__global__ __launch_bounds__(TPB) void diffusion_row_kernel(
    const int*   __restrict__ adj,   // [B, N, N] int32
    const float* __restrict__ u,     // [B, N, N] f32
    const float* __restrict__ q)     // [B, E] f32
{
    const int i   = blockIdx.x;      // row 0..N-1
    const int b   = blockIdx.y;      // batch
    const int tid = threadIdx.x;

    const float f    = g_f[b];
    const float fp   = g_fp[b];
    const float omf  = 1.0f - f;
    const float omfp = 1.0f - fp;

    const int*   arow = adj + ((size_t)b * NN + i) * NN;
    const float* urow = u   + ((size_t)b * NN + i) * NN;
    const float* qrow = q   + (size_t)b * EE + (size_t)i * (i - 1) / 2;

    float s = 0.0f;

    // Vector body: 16B-aligned int4/float4 on adj/u (row base is 8KB aligned).
    const int nv = i & ~3;
    for (int j = tid * 4; j < nv; j += TPB * 4) {
        const int4   a4 = *reinterpret_cast<const int4*>(arow + j);
        const float4 u4 = *reinterpret_cast<const float4*>(urow + j);
        const float  q0 = qrow[j + 0];
        const float  q1 = qrow[j + 1];
        const float  q2 = qrow[j + 2];
        const float  q3 = qrow[j + 3];
        s += edge_term(a4.x, u4.x, q0, f, omf, fp, omfp);
        s += edge_term(a4.y, u4.y, q1, f, omf, fp, omfp);
        s += edge_term(a4.z, u4.z, q2, f, omf, fp, omfp);
        s += edge_term(a4.w, u4.w, q3, f, omf, fp, omfp);
    }
    // Scalar tail (< 4 elements)
    for (int j = nv + tid; j < i; j += TPB)
        s += edge_term(arow[j], urow[j], qrow[j], f, omf, fp, omfp);

    __shared__ float sh[TPB];
    sh[tid] = s;
    __syncthreads();
    #pragma unroll
    for (int o = TPB / 2; o > 0; o >>= 1) {
        if (tid < o) sh[tid] += sh[tid + o];
        __syncthreads();
    }
    if (tid == 0) g_partial[(size_t)b * NN + i] = (double)sh[0];
}

__global__ __launch_bounds__(TPB) void diffusion_reduce_kernel(float* __restrict__ out)
{
    __shared__ double sh[TPB];
    double s = 0.0;
    for (int idx = threadIdx.x; idx < NBLK; idx += TPB) s += g_partial[idx];
    sh[threadIdx.x] = s;
    __syncthreads();
    #pragma unroll
    for (int o = TPB / 2; o > 0; o >>= 1) {
        if (threadIdx.x < o) sh[threadIdx.x] += sh[threadIdx.x + o];
        __syncthreads();
    }
    if (threadIdx.x == 0)
        out[0] = (float)(sh[0] / ((double)BB * (double)EE));
}

extern "C" void kernel_launch(void* const* d_in, const int* in_sizes, int n_in,
                              void* d_out, int out_size)
{
    const int*   adj = (const int*)  d_in[0];
    const int*   t   = (const int*)  d_in[1];
    const float* u   = (const float*)d_in[2];
    const float* q   = (const float*)d_in[3];
    float* out = (float*)d_out;

    diffusion_setup_kernel<<<1, 32>>>(t);
    dim3 grid(NN, BB);
    diffusion_row_kernel<<<grid, TPB>>>(adj, u, q);
    diffusion_reduce_kernel<<<1, TPB>>>(out);
}

// round 3
// speedup vs baseline: 17.3084x; 1.2578x over previous
#include <cuda_runtime.h>

#define BB 4
#define NN 2048
#define EE (NN*(NN-1)/2)        // 2,096,128
#define NPAIR (NN/2)            // 1024
#define NBLKS (NPAIR*BB)        // 4096
#define TPB 256
#define NWARP (TPB/32)

__device__ float g_partial[NBLKS];
__device__ unsigned int g_count = 0;

struct Consts { float f, omf, fp, omfp, rf, romf; };

__device__ __forceinline__ float edge_term(int a, float uu, float xv, const Consts& c)
{
    const float p1  = a ? c.omf : c.f;              // P(x_t = 1)
    const bool  x   = uu < p1;
    const float lik = x ? 0.99f : 0.01f;            // Qt[0][x_t, 1]
    const float pr  = a ? c.omfp : c.fp;            // Qt[t-1][a, 1]
    const float rev = ((a != 0) == x) ? c.romf : c.rf;  // 1 / Qt[t][a, x_t]
    const float qt  = lik * pr * rev;
    // softplus(-|x|) = log1p(exp(-|x|)) via EX2 + LG2
    const float sp  = 0.69314718056f * __log2f(1.0f + __expf(-fabsf(xv)));
    return fmaxf(xv, 0.0f) - xv * qt + sp;
}

__device__ __forceinline__ float row_sum(const int* __restrict__ arow,
                                         const float* __restrict__ urow,
                                         const float* __restrict__ qrow,
                                         int len, int tid, const Consts& c)
{
    float s = 0.0f;
    const int nv = len & ~3;
    for (int j = tid * 4; j < nv; j += TPB * 4) {
        const int4   a4 = *reinterpret_cast<const int4*>(arow + j);
        const float4 u4 = *reinterpret_cast<const float4*>(urow + j);
        const float q0 = qrow[j], q1 = qrow[j+1], q2 = qrow[j+2], q3 = qrow[j+3];
        s += edge_term(a4.x, u4.x, q0, c);
        s += edge_term(a4.y, u4.y, q1, c);
        s += edge_term(a4.z, u4.z, q2, c);
        s += edge_term(a4.w, u4.w, q3, c);
    }
    for (int j = nv + tid; j < len; j += TPB)
        s += edge_term(arow[j], urow[j], qrow[j], c);
    return s;
}

__global__ __launch_bounds__(TPB) void diffusion_fused_kernel(
    const int*   __restrict__ adj,   // [B, N, N] int32
    const int*   __restrict__ t,     // [B]
    const float* __restrict__ u,     // [B, N, N]
    const float* __restrict__ q,     // [B, E]
    float* __restrict__ out)
{
    const int p   = blockIdx.x;      // pair index: rows p and NN-1-p (total 2047 elems)
    const int b   = blockIdx.y;
    const int tid = threadIdx.x;

    // Per-batch flip probabilities: f = 0.5*(1 - 0.98^(t+1)); t-1 wraps to 999.
    const int tb = t[b];
    const double L2_098 = -0.0291463456595169;   // log2(0.98)
    const float pw  = exp2f((float)((double)(tb + 1) * L2_098));
    const int   tp  = (tb == 0) ? 999 : (tb - 1);
    const float pwp = exp2f((float)((double)(tp + 1) * L2_098));

    Consts c;
    c.f    = 0.5f * (1.0f - pw);
    c.omf  = 1.0f - c.f;
    c.fp   = 0.5f * (1.0f - pwp);
    c.omfp = 1.0f - c.fp;
    c.rf   = __fdividef(1.0f, c.f);
    c.romf = __fdividef(1.0f, c.omf);

    const int i1 = p;            // row length i1
    const int i2 = NN - 1 - p;   // row length i2

    const size_t bnn = (size_t)b * NN * NN;
    const size_t bee = (size_t)b * EE;

    float s = 0.0f;
    s += row_sum(adj + bnn + (size_t)i1 * NN, u + bnn + (size_t)i1 * NN,
                 q + bee + ((size_t)i1 * (size_t)(i1 - 1)) / 2, i1, tid, c);
    s += row_sum(adj + bnn + (size_t)i2 * NN, u + bnn + (size_t)i2 * NN,
                 q + bee + ((size_t)i2 * (size_t)(i2 - 1)) / 2, i2, tid, c);

    // warp shuffle reduce, then across warps
    #pragma unroll
    for (int o = 16; o > 0; o >>= 1)
        s += __shfl_xor_sync(0xFFFFFFFFu, s, o);

    __shared__ float wsum[NWARP];
    __shared__ bool  isLast;
    const int wid = tid >> 5, lid = tid & 31;
    if (lid == 0) wsum[wid] = s;
    __syncthreads();

    if (tid == 0) {
        float bs = 0.0f;
        #pragma unroll
        for (int w = 0; w < NWARP; w++) bs += wsum[w];
        g_partial[blockIdx.y * gridDim.x + blockIdx.x] = bs;
        __threadfence();
        unsigned int old = atomicAdd(&g_count, 1u);
        isLast = (old == (unsigned)(NBLKS - 1));
    }
    __syncthreads();

    // Last block performs the deterministic final reduction.
    if (isLast) {
        __shared__ double dsum[TPB];
        double ds = 0.0;
        for (int idx = tid; idx < NBLKS; idx += TPB)
            ds += (double)g_partial[idx];
        dsum[tid] = ds;
        __syncthreads();
        #pragma unroll
        for (int o = TPB / 2; o > 0; o >>= 1) {
            if (tid < o) dsum[tid] += dsum[tid + o];
            __syncthreads();
        }
        if (tid == 0) {
            out[0] = (float)(dsum[0] / ((double)BB * (double)EE));
            g_count = 0;   // reset for next graph replay
        }
    }
}

extern "C" void kernel_launch(void* const* d_in, const int* in_sizes, int n_in,
                              void* d_out, int out_size)
{
    const int*   adj = (const int*)  d_in[0];
    const int*   t   = (const int*)  d_in[1];
    const float* u   = (const float*)d_in[2];
    const float* q   = (const float*)d_in[3];
    float* out = (float*)d_out;

    dim3 grid(NPAIR, BB);
    diffusion_fused_kernel<<<grid, TPB>>>(adj, t, u, q, out);
}

// round 5
// speedup vs baseline: 19.9508x; 1.1527x over previous
#include <cuda_runtime.h>

#define BB 4
#define NN 2048
#define EE (NN*(NN-1)/2)        // 2,096,128
#define NPAIR (NN/2)            // 1024
#define NBLKS (NPAIR*BB)        // 4096
#define TPB 256
#define NWARP (TPB/32)

__device__ float g_partial[NBLKS];
__device__ unsigned int g_count = 0;

struct Consts {
    float f, omf;
    float qt00, qt01, qt10, qt11;   // qt[a][x] = lik(x)*pr(a)/ev(a==x)
};

__device__ __forceinline__ float edge_term(int a, float uu, float xv, const Consts& c)
{
    const float p1 = a ? c.omf : c.f;            // P(x_t = 1)
    const bool  x  = uu < p1;
    const float q0 = x ? c.qt01 : c.qt00;        // a = 0 branch
    const float q1 = x ? c.qt11 : c.qt10;        // a = 1 branch
    const float qt = a ? q1 : q0;
    // softplus(-|x|) = log1p(exp(-|x|)) via EX2 + LG2
    const float sp = 0.69314718056f * __log2f(1.0f + __expf(-fabsf(xv)));
    return fmaxf(xv, 0.0f) - xv * qt + sp;
}

// One straight-line pass over a row prefix of length len (<= 2048):
// thread tid owns elements [8*tid, 8*tid+8). All 12 loads per full group are
// issued branch-free and back-to-back for maximal MLP.
__device__ __forceinline__ float row_sum(const int* __restrict__ arow,
                                         const float* __restrict__ urow,
                                         const float* __restrict__ qrow,
                                         int len, int tid, const Consts& c)
{
    const int g = tid * 8;
    float s = 0.0f;
    if (g + 8 <= len) {
        const int4   a0 = *reinterpret_cast<const int4*>(arow + g);
        const int4   a1 = *reinterpret_cast<const int4*>(arow + g + 4);
        const float4 u0 = *reinterpret_cast<const float4*>(urow + g);
        const float4 u1 = *reinterpret_cast<const float4*>(urow + g + 4);
        const float  x0 = qrow[g + 0], x1 = qrow[g + 1], x2 = qrow[g + 2], x3 = qrow[g + 3];
        const float  x4 = qrow[g + 4], x5 = qrow[g + 5], x6 = qrow[g + 6], x7 = qrow[g + 7];
        s += edge_term(a0.x, u0.x, x0, c);
        s += edge_term(a0.y, u0.y, x1, c);
        s += edge_term(a0.z, u0.z, x2, c);
        s += edge_term(a0.w, u0.w, x3, c);
        s += edge_term(a1.x, u1.x, x4, c);
        s += edge_term(a1.y, u1.y, x5, c);
        s += edge_term(a1.z, u1.z, x6, c);
        s += edge_term(a1.w, u1.w, x7, c);
    } else if (g < len) {
        for (int j = g; j < len; j++)
            s += edge_term(arow[j], urow[j], qrow[j], c);
    }
    return s;
}

__global__ __launch_bounds__(TPB) void diffusion_fused_kernel(
    const int*   __restrict__ adj,   // [B, N, N] int32
    const int*   __restrict__ t,     // [B]
    const float* __restrict__ u,     // [B, N, N]
    const float* __restrict__ q,     // [B, E]
    float* __restrict__ out)
{
    const int p   = blockIdx.x;      // pair: rows p and NN-1-p (2047 elems total)
    const int b   = blockIdx.y;
    const int tid = threadIdx.x;

    // Per-batch flip probabilities: f = 0.5*(1 - 0.98^(t+1)); t-1 wraps to 999.
    const int tb = t[b];
    const double L2_098 = -0.0291463456595169;   // log2(0.98)
    const float pw  = exp2f((float)((double)(tb + 1) * L2_098));
    const int   tp  = (tb == 0) ? 999 : (tb - 1);
    const float pwp = exp2f((float)((double)(tp + 1) * L2_098));

    Consts c;
    c.f   = 0.5f * (1.0f - pw);
    c.omf = 1.0f - c.f;
    const float fp   = 0.5f * (1.0f - pwp);
    const float omfp = 1.0f - fp;
    const float rf   = __fdividef(1.0f, c.f);
    const float romf = __fdividef(1.0f, c.omf);
    // qt[a][x] = lik(x) * pr(a) / ev(a==x);  ev: equal -> omf, diff -> f
    c.qt00 = 0.01f * fp   * romf;
    c.qt01 = 0.99f * fp   * rf;
    c.qt10 = 0.01f * omfp * rf;
    c.qt11 = 0.99f * omfp * romf;

    const int i1 = p;
    const int i2 = NN - 1 - p;
    const size_t bnn = (size_t)b * NN * NN;
    const size_t bee = (size_t)b * EE;

    float s = 0.0f;
    s += row_sum(adj + bnn + (size_t)i1 * NN, u + bnn + (size_t)i1 * NN,
                 q + bee + ((size_t)i1 * (size_t)(i1 - 1)) / 2, i1, tid, c);
    s += row_sum(adj + bnn + (size_t)i2 * NN, u + bnn + (size_t)i2 * NN,
                 q + bee + ((size_t)i2 * (size_t)(i2 - 1)) / 2, i2, tid, c);

    #pragma unroll
    for (int o = 16; o > 0; o >>= 1)
        s += __shfl_xor_sync(0xFFFFFFFFu, s, o);

    __shared__ float wsum[NWARP];
    __shared__ bool  isLast;
    const int wid = tid >> 5, lid = tid & 31;
    if (lid == 0) wsum[wid] = s;
    __syncthreads();

    if (tid == 0) {
        float bs = 0.0f;
        #pragma unroll
        for (int w = 0; w < NWARP; w++) bs += wsum[w];
        g_partial[blockIdx.y * gridDim.x + blockIdx.x] = bs;
        __threadfence();
        unsigned int old = atomicAdd(&g_count, 1u);
        isLast = (old == (unsigned)(NBLKS - 1));
    }
    __syncthreads();

    if (isLast) {
        __shared__ double dsum[TPB];
        double ds = 0.0;
        for (int idx = tid; idx < NBLKS; idx += TPB)
            ds += (double)g_partial[idx];
        dsum[tid] = ds;
        __syncthreads();
        #pragma unroll
        for (int o = TPB / 2; o > 0; o >>= 1) {
            if (tid < o) dsum[tid] += dsum[tid + o];
            __syncthreads();
        }
        if (tid == 0) {
            out[0] = (float)(dsum[0] / ((double)BB * (double)EE));
            g_count = 0;   // reset for next graph replay
        }
    }
}

extern "C" void kernel_launch(void* const* d_in, const int* in_sizes, int n_in,
                              void* d_out, int out_size)
{
    const int*   adj = (const int*)  d_in[0];
    const int*   t   = (const int*)  d_in[1];
    const float* u   = (const float*)d_in[2];
    const float* q   = (const float*)d_in[3];
    float* out = (float*)d_out;

    dim3 grid(NPAIR, BB);
    diffusion_fused_kernel<<<grid, TPB>>>(adj, t, u, q, out);
}